// round 2
// baseline (speedup 1.0000x reference)
#include <cuda_runtime.h>
#include <cuda_bf16.h>
#include <math.h>

// Problem constants (fixed by the dataset)
#define NODES_MAX 100000
#define EDGES_MAX 1600000
#define F_IN   128
#define F_HID  64     // 16 float4
#define F_OUT  47
#define F_OUTP 48     // padded to 12 float4

// ---------------------------------------------------------------------------
// Device scratch (no cudaMalloc allowed)
// ---------------------------------------------------------------------------
__device__ float g_xw1 [NODES_MAX * F_HID];   // x @ W1
__device__ float g_agg1[NODES_MAX * F_HID];   // scatter accum -> becomes h after finalize
__device__ float g_xw2 [NODES_MAX * F_OUTP];  // h @ W2 (col 47 = 0)
__device__ float g_agg2[NODES_MAX * F_OUTP];  // scatter accum layer 2
__device__ float g_deg [NODES_MAX];
__device__ float g_dinv[NODES_MAX];
__device__ float g_norm[EDGES_MAX];

// ---------------------------------------------------------------------------
// Helpers
// ---------------------------------------------------------------------------
__device__ __forceinline__ void red_add_v4(float* p, float4 v) {
    asm volatile("red.global.add.v4.f32 [%0], {%1,%2,%3,%4};"
                 :: "l"(p), "f"(v.x), "f"(v.y), "f"(v.z), "f"(v.w) : "memory");
}

__global__ void zero_v4_kernel(float4* p, int n4) {
    int i = blockIdx.x * blockDim.x + threadIdx.x;
    if (i < n4) p[i] = make_float4(0.f, 0.f, 0.f, 0.f);
}

__global__ void init_deg_kernel(int n) {
    int i = blockIdx.x * blockDim.x + threadIdx.x;
    if (i < n) g_deg[i] = 1.0f;              // self-loop
}

__global__ void deg_accum_kernel(const int* __restrict__ dst, int e) {
    int i = blockIdx.x * blockDim.x + threadIdx.x;
    if (i < e) atomicAdd(&g_deg[dst[i]], 1.0f);
}

__global__ void dinv_kernel(int n) {
    int i = blockIdx.x * blockDim.x + threadIdx.x;
    if (i < n) g_dinv[i] = rsqrtf(g_deg[i]);
}

__global__ void norm_kernel(const int* __restrict__ src, const int* __restrict__ dst, int e) {
    int i = blockIdx.x * blockDim.x + threadIdx.x;
    if (i < e) g_norm[i] = g_dinv[src[i]] * g_dinv[dst[i]];
}

// ---------------------------------------------------------------------------
// GEMM1: xw1[n,64] = x[n,128] @ W1[128,64]
// block = 256 threads, 16 rows per block. W1 fully in SMEM.
// ---------------------------------------------------------------------------
__global__ __launch_bounds__(256) void gemm1_kernel(const float* __restrict__ x,
                                                    const float* __restrict__ W1,
                                                    int n) {
    __shared__ float Ws[F_IN * F_HID];        // 32 KB
    __shared__ float Xs[16][F_IN];            // 8 KB
    int tid = threadIdx.x;
    int row0 = blockIdx.x * 16;

    for (int i = tid; i < F_IN * F_HID; i += 256) Ws[i] = W1[i];
    for (int i = tid; i < 16 * F_IN; i += 256) {
        int r = i >> 7, k = i & 127;
        int gr = row0 + r;
        Xs[r][k] = (gr < n) ? x[gr * F_IN + k] : 0.f;
    }
    __syncthreads();

    int c  = tid & 63;   // output col
    int ty = tid >> 6;   // 0..3 -> rows ty, ty+4, ty+8, ty+12
    float acc0 = 0.f, acc1 = 0.f, acc2 = 0.f, acc3 = 0.f;
    #pragma unroll 8
    for (int k = 0; k < F_IN; k++) {
        float w = Ws[k * F_HID + c];
        acc0 = fmaf(Xs[ty     ][k], w, acc0);
        acc1 = fmaf(Xs[ty +  4][k], w, acc1);
        acc2 = fmaf(Xs[ty +  8][k], w, acc2);
        acc3 = fmaf(Xs[ty + 12][k], w, acc3);
    }
    float accs[4] = {acc0, acc1, acc2, acc3};
    #pragma unroll
    for (int j = 0; j < 4; j++) {
        int r = row0 + ty + j * 4;
        if (r < n) g_xw1[r * F_HID + c] = accs[j];
    }
}

// ---------------------------------------------------------------------------
// Scatter layer 1: agg1[dst] += xw1[src] * norm ; 16 float4 per edge
// ---------------------------------------------------------------------------
__global__ __launch_bounds__(256) void scatter1_kernel(const int* __restrict__ src,
                                                       const int* __restrict__ dst,
                                                       int e) {
    int i = blockIdx.x * blockDim.x + threadIdx.x;
    if (i >= e * 16) return;
    int ed = i >> 4, c = i & 15;
    int s = src[ed], d = dst[ed];
    float nrm = g_norm[ed];
    float4 v = reinterpret_cast<const float4*>(g_xw1)[s * 16 + c];
    v.x *= nrm; v.y *= nrm; v.z *= nrm; v.w *= nrm;
    red_add_v4(&g_agg1[d * F_HID + c * 4], v);
}

// ---------------------------------------------------------------------------
// Finalize layer 1: h = relu(agg1 + xw1 * (1/deg) + b1)  (in place into agg1)
// ---------------------------------------------------------------------------
__global__ __launch_bounds__(256) void finalize1_kernel(const float* __restrict__ b1, int n) {
    int i = blockIdx.x * blockDim.x + threadIdx.x;
    if (i >= n * F_HID) return;
    int r = i >> 6, c = i & 63;
    float v = g_agg1[i] + g_xw1[i] * (1.0f / g_deg[r]) + b1[c];
    g_agg1[i] = fmaxf(v, 0.f);
}

// ---------------------------------------------------------------------------
// GEMM2: xw2[n,48] = h[n,64] @ W2[64,47], padded col 47 = 0
// block = 192 threads (48 cols x 4), 16 rows per block.
// ---------------------------------------------------------------------------
__global__ __launch_bounds__(192) void gemm2_kernel(const float* __restrict__ W2, int n) {
    __shared__ float Ws[F_HID * F_OUTP];      // 12 KB (padded)
    __shared__ float Hs[16][F_HID];           // 4 KB
    int tid = threadIdx.x;
    int row0 = blockIdx.x * 16;

    for (int i = tid; i < F_HID * F_OUTP; i += 192) {
        int k = i / F_OUTP, c = i % F_OUTP;
        Ws[i] = (c < F_OUT) ? W2[k * F_OUT + c] : 0.f;
    }
    for (int i = tid; i < 16 * F_HID; i += 192) {
        int r = i >> 6, k = i & 63;
        int gr = row0 + r;
        Hs[r][k] = (gr < n) ? g_agg1[gr * F_HID + k] : 0.f;
    }
    __syncthreads();

    int c  = tid % 48;
    int ty = tid / 48;  // 0..3
    float acc0 = 0.f, acc1 = 0.f, acc2 = 0.f, acc3 = 0.f;
    #pragma unroll 8
    for (int k = 0; k < F_HID; k++) {
        float w = Ws[k * F_OUTP + c];
        acc0 = fmaf(Hs[ty     ][k], w, acc0);
        acc1 = fmaf(Hs[ty +  4][k], w, acc1);
        acc2 = fmaf(Hs[ty +  8][k], w, acc2);
        acc3 = fmaf(Hs[ty + 12][k], w, acc3);
    }
    float accs[4] = {acc0, acc1, acc2, acc3};
    #pragma unroll
    for (int j = 0; j < 4; j++) {
        int r = row0 + ty + j * 4;
        if (r < n) g_xw2[r * F_OUTP + c] = accs[j];
    }
}

// ---------------------------------------------------------------------------
// Scatter layer 2: agg2[dst] += xw2[src] * norm ; 12 float4 per edge
// ---------------------------------------------------------------------------
__global__ __launch_bounds__(256) void scatter2_kernel(const int* __restrict__ src,
                                                       const int* __restrict__ dst,
                                                       int e) {
    int i = blockIdx.x * blockDim.x + threadIdx.x;
    if (i >= e * 12) return;
    int ed = i / 12, c = i - ed * 12;
    int s = src[ed], d = dst[ed];
    float nrm = g_norm[ed];
    float4 v = reinterpret_cast<const float4*>(g_xw2)[s * 12 + c];
    v.x *= nrm; v.y *= nrm; v.z *= nrm; v.w *= nrm;
    red_add_v4(&g_agg2[d * F_OUTP + c * 4], v);
}

// ---------------------------------------------------------------------------
// Final: out = log_softmax(agg2 + xw2*(1/deg) + b2) ; one warp per row
// ---------------------------------------------------------------------------
__global__ __launch_bounds__(256) void final_kernel(const float* __restrict__ b2,
                                                    float* __restrict__ out, int n) {
    int warp = (blockIdx.x * blockDim.x + threadIdx.x) >> 5;
    int lane = threadIdx.x & 31;
    if (warp >= n) return;

    float inv = 1.0f / g_deg[warp];
    int c0 = lane, c1 = lane + 32;
    float v0 = g_agg2[warp * F_OUTP + c0] + g_xw2[warp * F_OUTP + c0] * inv + b2[c0];
    float v1 = -3.0e38f;
    if (c1 < F_OUT)
        v1 = g_agg2[warp * F_OUTP + c1] + g_xw2[warp * F_OUTP + c1] * inv + b2[c1];

    // warp max
    float m = fmaxf(v0, v1);
    #pragma unroll
    for (int o = 16; o > 0; o >>= 1)
        m = fmaxf(m, __shfl_xor_sync(0xFFFFFFFFu, m, o));
    // warp sum of exp
    float s = expf(v0 - m) + ((c1 < F_OUT) ? expf(v1 - m) : 0.f);
    #pragma unroll
    for (int o = 16; o > 0; o >>= 1)
        s += __shfl_xor_sync(0xFFFFFFFFu, s, o);
    float lse = m + logf(s);

    out[warp * F_OUT + c0] = v0 - lse;
    if (c1 < F_OUT) out[warp * F_OUT + c1] = v1 - lse;
}

// ---------------------------------------------------------------------------
// Launch
// ---------------------------------------------------------------------------
extern "C" void kernel_launch(void* const* d_in, const int* in_sizes, int n_in,
                              void* d_out, int out_size) {
    const float* x  = (const float*)d_in[0];
    const int*   ei = (const int*)  d_in[1];
    const float* W1 = (const float*)d_in[2];
    const float* b1 = (const float*)d_in[3];
    const float* W2 = (const float*)d_in[4];
    const float* b2 = (const float*)d_in[5];
    float* out = (float*)d_out;

    int n = in_sizes[0] / F_IN;       // 100000
    int e = in_sizes[1] / 2;          // 1600000
    const int* src = ei;
    const int* dst = ei + e;

    float4* agg1_4; cudaGetSymbolAddress((void**)&agg1_4, g_agg1);
    float4* agg2_4; cudaGetSymbolAddress((void**)&agg2_4, g_agg2);

    const int B = 256;
    // zero accumulators
    {
        int n4 = n * F_HID / 4;
        zero_v4_kernel<<<(n4 + B - 1) / B, B>>>(agg1_4, n4);
        n4 = n * F_OUTP / 4;
        zero_v4_kernel<<<(n4 + B - 1) / B, B>>>(agg2_4, n4);
    }
    // degree / norm
    init_deg_kernel<<<(n + B - 1) / B, B>>>(n);
    deg_accum_kernel<<<(e + B - 1) / B, B>>>(dst, e);
    dinv_kernel<<<(n + B - 1) / B, B>>>(n);
    norm_kernel<<<(e + B - 1) / B, B>>>(src, dst, e);

    // layer 1
    gemm1_kernel<<<(n + 15) / 16, 256>>>(x, W1, n);
    {
        int work = e * 16;
        scatter1_kernel<<<(work + B - 1) / B, B>>>(src, dst, e);
    }
    finalize1_kernel<<<(n * F_HID + B - 1) / B, B>>>(b1, n);

    // layer 2
    gemm2_kernel<<<(n + 15) / 16, 192>>>(W2, n);
    {
        int work = e * 12;
        scatter2_kernel<<<(work + B - 1) / B, B>>>(src, dst, e);
    }
    final_kernel<<<(n * 32 + B - 1) / B, B>>>(b2, out, n);
}

// round 4
// speedup vs baseline: 1.1833x; 1.1833x over previous
#include <cuda_runtime.h>
#include <cuda_bf16.h>
#include <math.h>

// Problem constants (fixed by the dataset)
#define NODES_MAX 100000
#define EDGES_MAX 1600000
#define F_IN   128
#define F_HID  64     // 32 float2
#define F_OUT  47
#define F_OUTP 48     // 24 float2 / 12 float4

// ---------------------------------------------------------------------------
// Device scratch (no cudaMalloc allowed)
// ---------------------------------------------------------------------------
__device__ float g_y1 [NODES_MAX * F_HID];    // (x @ W1) * dinv[row]
__device__ float g_h  [NODES_MAX * F_HID];    // hidden after layer 1
__device__ float g_y2 [NODES_MAX * F_OUTP];   // (h @ W2) * dinv[row], col 47 = 0
__device__ float g_dinv[NODES_MAX];
__device__ int   g_degi[NODES_MAX];
__device__ int   g_off [NODES_MAX + 1];
__device__ int   g_cursor[NODES_MAX];
__device__ int   g_csrc[EDGES_MAX];           // CSR by dst: source node ids

// ---------------------------------------------------------------------------
// CSR build
// ---------------------------------------------------------------------------
__global__ void zero_degi_kernel(int n) {
    int i = blockIdx.x * blockDim.x + threadIdx.x;
    if (i < n) g_degi[i] = 0;
}

__global__ void count_kernel(const int* __restrict__ dst, int e) {
    int i = blockIdx.x * blockDim.x + threadIdx.x;
    if (i < e) atomicAdd(&g_degi[dst[i]], 1);
}

// Single-block chunked exclusive scan over g_degi -> g_off, g_cursor.
// Also computes dinv = rsqrt(deg+1) (self-loop included).
__global__ __launch_bounds__(1024) void scan_kernel(int n, int e) {
    __shared__ int ssum[1024];
    int t = threadIdx.x;
    const int CH = (n + 1023) / 1024;
    int lo = t * CH;
    int hi = min(lo + CH, n);

    int s = 0;
    for (int i = lo; i < hi; i++) s += g_degi[i];
    ssum[t] = s;
    __syncthreads();
    // Hillis-Steele inclusive scan
    for (int off = 1; off < 1024; off <<= 1) {
        int v = (t >= off) ? ssum[t - off] : 0;
        __syncthreads();
        ssum[t] += v;
        __syncthreads();
    }
    int run = ssum[t] - s;   // exclusive prefix for this chunk
    for (int i = lo; i < hi; i++) {
        g_off[i] = run;
        g_cursor[i] = run;
        int d = g_degi[i];
        run += d;
        g_dinv[i] = rsqrtf((float)(d + 1));
    }
    if (t == 1023) g_off[n] = e;
}

__global__ void fill_kernel(const int* __restrict__ src, const int* __restrict__ dst, int e) {
    int i = blockIdx.x * blockDim.x + threadIdx.x;
    if (i < e) {
        int d = dst[i];
        int pos = atomicAdd(&g_cursor[d], 1);
        g_csrc[pos] = src[i];
    }
}

// ---------------------------------------------------------------------------
// GEMM1: y1[n,64] = (x[n,128] @ W1[128,64]) * dinv[row]
// block = 256 threads (16 tx x 16 ty... actually tx 0..15 cols-quads,
// ty 0..3 row-quads x4 rows). Tile: 32 rows x 64 cols, 4x4 microtile.
// ---------------------------------------------------------------------------
#define XS_LD 129   // padded stride (conflict-free column reads)
__global__ __launch_bounds__(256) void gemm1_kernel(const float* __restrict__ x,
                                                    const float* __restrict__ W1,
                                                    int n) {
    __shared__ float Ws[F_IN * F_HID];        // 32 KB, [k][c]
    __shared__ float Xs[32 * XS_LD];          // ~16.5 KB, [r][k] padded
    int tid = threadIdx.x;
    int row0 = blockIdx.x * 32;

    for (int i = tid; i < F_IN * F_HID; i += 256) Ws[i] = W1[i];
    // 32 rows x 128 cols, coalesced global read (consecutive k per warp)
    for (int i = tid; i < 32 * F_IN; i += 256) {
        int r = i >> 7, k = i & 127;
        int gr = row0 + r;
        Xs[r * XS_LD + k] = (gr < n) ? x[gr * F_IN + k] : 0.f;
    }
    __syncthreads();

    int tx = tid & 15;        // col quad: cols tx*4 .. tx*4+3
    int ty = tid >> 4;        // row quad: rows ty*4 .. ty*4+3 (ty 0..15? no: 256/16=16)
    // 16 ty x 16 tx would be 64 rows; we have 32 rows -> ty 0..7, 2 warps worth.
    // Recompute: 256 threads = 16 tx * 16 ty -> need 64 rows. Use 8 ty covering 32 rows
    // with 128 threads? Keep 256: ty 0..15, rows = ty*2 (2 rows per thread x4 cols? )
    // Simpler: ty 0..7 handles 4 rows each (32 rows), tx 0..15 (64 cols), = 128 lanes *2?
    // -> Use microtile 2 rows x 4 cols per thread at 256 threads: ty 0..15, 2 rows each.
    ty = tid >> 4;            // 0..15, rows ty*2, ty*2+1

    float4 acc0 = make_float4(0.f, 0.f, 0.f, 0.f);
    float4 acc1 = make_float4(0.f, 0.f, 0.f, 0.f);
    const float4* Ws4 = reinterpret_cast<const float4*>(Ws);
    int r0 = ty * 2, r1 = ty * 2 + 1;
    #pragma unroll 4
    for (int k = 0; k < F_IN; k++) {
        float4 w = Ws4[k * 16 + tx];
        float a0 = Xs[r0 * XS_LD + k];
        float a1 = Xs[r1 * XS_LD + k];
        acc0.x = fmaf(a0, w.x, acc0.x); acc0.y = fmaf(a0, w.y, acc0.y);
        acc0.z = fmaf(a0, w.z, acc0.z); acc0.w = fmaf(a0, w.w, acc0.w);
        acc1.x = fmaf(a1, w.x, acc1.x); acc1.y = fmaf(a1, w.y, acc1.y);
        acc1.z = fmaf(a1, w.z, acc1.z); acc1.w = fmaf(a1, w.w, acc1.w);
    }
    int gr0 = row0 + r0, gr1 = row0 + r1;
    float4* y4 = reinterpret_cast<float4*>(g_y1);
    if (gr0 < n) {
        float di = g_dinv[gr0];
        acc0.x *= di; acc0.y *= di; acc0.z *= di; acc0.w *= di;
        y4[gr0 * 16 + tx] = acc0;
    }
    if (gr1 < n) {
        float di = g_dinv[gr1];
        acc1.x *= di; acc1.y *= di; acc1.z *= di; acc1.w *= di;
        y4[gr1 * 16 + tx] = acc1;
    }
}

// ---------------------------------------------------------------------------
// Aggregation layer 1 (atomic-free, warp per dst node):
//   h[d] = relu(dinv[d] * (sum_{s in in(d)} y1[s] + y1[d]) + b1)
// Lane l owns float2 (cols 2l, 2l+1). One LDG.64 x 32 lanes = full 256B row/edge.
// ---------------------------------------------------------------------------
__global__ __launch_bounds__(256) void agg1_kernel(const float* __restrict__ b1, int n) {
    int w = (blockIdx.x * blockDim.x + threadIdx.x) >> 5;
    int l = threadIdx.x & 31;
    if (w >= n) return;
    const float2* y = reinterpret_cast<const float2*>(g_y1);

    float2 acc = y[w * 32 + l];       // self-loop term
    int beg = g_off[w], end = g_off[w + 1];
    int j = beg;
    for (; j + 1 < end; j += 2) {
        int s0 = g_csrc[j], s1 = g_csrc[j + 1];
        float2 v0 = y[s0 * 32 + l];
        float2 v1 = y[s1 * 32 + l];
        acc.x += v0.x + v1.x;
        acc.y += v0.y + v1.y;
    }
    if (j < end) {
        int s = g_csrc[j];
        float2 v = y[s * 32 + l];
        acc.x += v.x; acc.y += v.y;
    }
    float di = g_dinv[w];
    float2 h;
    h.x = fmaxf(fmaf(di, acc.x, b1[2 * l    ]), 0.f);
    h.y = fmaxf(fmaf(di, acc.y, b1[2 * l + 1]), 0.f);
    reinterpret_cast<float2*>(g_h)[w * 32 + l] = h;
}

// ---------------------------------------------------------------------------
// GEMM2: y2[n,48] = (h[n,64] @ W2pad[64,48]) * dinv[row], col 47 = 0
// block = 192 threads: tx 0..11 (col quads), ty 0..15 (4 rows each) -> 64x48 tile
// ---------------------------------------------------------------------------
#define HS_LD 65
__global__ __launch_bounds__(192) void gemm2_kernel(const float* __restrict__ W2, int n) {
    __shared__ float Ws[F_HID * F_OUTP];      // 12 KB, [k][c] padded
    __shared__ float Hs[64 * HS_LD];          // ~16.6 KB, [r][k] padded
    int tid = threadIdx.x;
    int row0 = blockIdx.x * 64;

    for (int i = tid; i < F_HID * F_OUTP; i += 192) {
        int k = i / F_OUTP, c = i - k * F_OUTP;
        Ws[i] = (c < F_OUT) ? W2[k * F_OUT + c] : 0.f;
    }
    for (int i = tid; i < 64 * F_HID; i += 192) {
        int r = i >> 6, k = i & 63;
        int gr = row0 + r;
        Hs[r * HS_LD + k] = (gr < n) ? g_h[gr * F_HID + k] : 0.f;
    }
    __syncthreads();

    int tx = tid % 12;        // cols tx*4..tx*4+3
    int ty = tid / 12;        // 0..15, rows ty*4..ty*4+3
    float4 acc[4];
    #pragma unroll
    for (int i = 0; i < 4; i++) acc[i] = make_float4(0.f, 0.f, 0.f, 0.f);
    const float4* Ws4 = reinterpret_cast<const float4*>(Ws);

    #pragma unroll 4
    for (int k = 0; k < F_HID; k++) {
        float4 wv = Ws4[k * 12 + tx];
        #pragma unroll
        for (int i = 0; i < 4; i++) {
            float a = Hs[(ty * 4 + i) * HS_LD + k];
            acc[i].x = fmaf(a, wv.x, acc[i].x);
            acc[i].y = fmaf(a, wv.y, acc[i].y);
            acc[i].z = fmaf(a, wv.z, acc[i].z);
            acc[i].w = fmaf(a, wv.w, acc[i].w);
        }
    }
    float4* y4 = reinterpret_cast<float4*>(g_y2);
    #pragma unroll
    for (int i = 0; i < 4; i++) {
        int r = row0 + ty * 4 + i;
        if (r < n) {
            float di = g_dinv[r];
            float4 v = acc[i];
            v.x *= di; v.y *= di; v.z *= di; v.w *= di;
            y4[r * 12 + tx] = v;
        }
    }
}

// ---------------------------------------------------------------------------
// Aggregation layer 2 + bias + log_softmax (warp per node):
//   z[d] = dinv[d] * (sum y2[s] + y2[d]) + b2 ; out = z - logsumexp(z)
// Lanes 0..23 own float2 (cols 2l, 2l+1); col 47 is padding (excluded).
// ---------------------------------------------------------------------------
__global__ __launch_bounds__(256) void agg2_kernel(const float* __restrict__ b2,
                                                   float* __restrict__ out, int n) {
    int w = (blockIdx.x * blockDim.x + threadIdx.x) >> 5;
    int l = threadIdx.x & 31;
    if (w >= n) return;
    const float2* y = reinterpret_cast<const float2*>(g_y2);
    bool act = (l < 24);

    float2 acc = make_float2(0.f, 0.f);
    if (act) acc = y[w * 24 + l];     // self-loop term
    int beg = g_off[w], end = g_off[w + 1];
    int j = beg;
    for (; j + 1 < end; j += 2) {
        int s0 = g_csrc[j], s1 = g_csrc[j + 1];
        if (act) {
            float2 v0 = y[s0 * 24 + l];
            float2 v1 = y[s1 * 24 + l];
            acc.x += v0.x + v1.x;
            acc.y += v0.y + v1.y;
        }
    }
    if (j < end) {
        int s = g_csrc[j];
        if (act) {
            float2 v = y[s * 24 + l];
            acc.x += v.x; acc.y += v.y;
        }
    }

    float di = g_dinv[w];
    float vx = -3.0e38f, vy = -3.0e38f;
    if (act) {
        vx = fmaf(di, acc.x, b2[2 * l]);
        if (2 * l + 1 < F_OUT) vy = fmaf(di, acc.y, b2[2 * l + 1]);
    }
    // warp max
    float m = fmaxf(vx, vy);
    #pragma unroll
    for (int o = 16; o > 0; o >>= 1)
        m = fmaxf(m, __shfl_xor_sync(0xFFFFFFFFu, m, o));
    // warp sum of exp (inactive/padded contribute 0)
    float s = 0.f;
    if (act) {
        s = expf(vx - m);
        if (2 * l + 1 < F_OUT) s += expf(vy - m);
    }
    #pragma unroll
    for (int o = 16; o > 0; o >>= 1)
        s += __shfl_xor_sync(0xFFFFFFFFu, s, o);
    float lse = m + logf(s);

    if (act) {
        out[w * F_OUT + 2 * l] = vx - lse;
        if (2 * l + 1 < F_OUT) out[w * F_OUT + 2 * l + 1] = vy - lse;
    }
}

// ---------------------------------------------------------------------------
// Launch
// ---------------------------------------------------------------------------
extern "C" void kernel_launch(void* const* d_in, const int* in_sizes, int n_in,
                              void* d_out, int out_size) {
    const float* x  = (const float*)d_in[0];
    const int*   ei = (const int*)  d_in[1];
    const float* W1 = (const float*)d_in[2];
    const float* b1 = (const float*)d_in[3];
    const float* W2 = (const float*)d_in[4];
    const float* b2 = (const float*)d_in[5];
    float* out = (float*)d_out;

    int n = in_sizes[0] / F_IN;       // 100000
    int e = in_sizes[1] / 2;          // 1600000
    const int* src = ei;
    const int* dst = ei + e;

    const int B = 256;
    // CSR build (per-call; deterministic work)
    zero_degi_kernel<<<(n + B - 1) / B, B>>>(n);
    count_kernel<<<(e + B - 1) / B, B>>>(dst, e);
    scan_kernel<<<1, 1024>>>(n, e);
    fill_kernel<<<(e + B - 1) / B, B>>>(src, dst, e);

    // layer 1
    gemm1_kernel<<<(n + 31) / 32, 256>>>(x, W1, n);
    agg1_kernel<<<(n * 32 + B - 1) / B, B>>>(b1, n);     // warp per node

    // layer 2
    gemm2_kernel<<<(n + 63) / 64, 192>>>(W2, n);
    agg2_kernel<<<(n * 32 + B - 1) / B, B>>>(b2, out, n); // warp per node + softmax
}

// round 5
// speedup vs baseline: 2.1701x; 1.8340x over previous
#include <cuda_runtime.h>
#include <cuda_bf16.h>
#include <math.h>

// Problem constants (fixed by the dataset)
#define NODES_MAX 100000
#define EDGES_MAX 1600000
#define F_IN   128
#define F_HID  64     // 32 float2
#define F_OUT  47
#define F_OUTP 48     // 24 float2 / 12 float4

#define SCAN_TPB 512
#define SCAN_NB_MAX 256

// ---------------------------------------------------------------------------
// Device scratch (no cudaMalloc allowed)
// ---------------------------------------------------------------------------
__device__ float g_y1 [NODES_MAX * F_HID];    // raw x @ W1 (no dinv)
__device__ float g_h  [NODES_MAX * F_HID];    // hidden after layer 1
__device__ float g_y2 [NODES_MAX * F_OUTP];   // (h @ W2) * dinv[row], col 47 = 0
__device__ float g_dinv[NODES_MAX];
__device__ int   g_degi[NODES_MAX];
__device__ int   g_off [NODES_MAX + 1];
__device__ int   g_cursor[NODES_MAX];
__device__ int   g_csrc[EDGES_MAX];           // CSR by dst: source node ids
__device__ int   g_bsum [SCAN_NB_MAX];
__device__ int   g_bscan[SCAN_NB_MAX];

// ---------------------------------------------------------------------------
// CSR build
// ---------------------------------------------------------------------------
__global__ void zero_degi_kernel(int n) {
    int i = blockIdx.x * blockDim.x + threadIdx.x;
    if (i < n) g_degi[i] = 0;
}

__global__ void count_kernel(const int* __restrict__ dst, int e) {
    int i = blockIdx.x * blockDim.x + threadIdx.x;
    if (i < e) atomicAdd(&g_degi[dst[i]], 1);
}

// Multi-block scan, stage 1: per-chunk (SCAN_TPB elems) partial sums.
__global__ __launch_bounds__(SCAN_TPB) void scan_partial_kernel(int n) {
    __shared__ int sred[SCAN_TPB];
    int t = threadIdx.x;
    int i = blockIdx.x * SCAN_TPB + t;
    sred[t] = (i < n) ? g_degi[i] : 0;
    __syncthreads();
    for (int o = SCAN_TPB / 2; o > 0; o >>= 1) {
        if (t < o) sred[t] += sred[t + o];
        __syncthreads();
    }
    if (t == 0) g_bsum[blockIdx.x] = sred[0];
}

// Stage 2: single small block scans the partials (exclusive).
__global__ __launch_bounds__(SCAN_NB_MAX) void scan_tops_kernel(int nb, int n, int e) {
    __shared__ int s[SCAN_NB_MAX];
    int t = threadIdx.x;
    int v = (t < nb) ? g_bsum[t] : 0;
    s[t] = v;
    __syncthreads();
    for (int o = 1; o < SCAN_NB_MAX; o <<= 1) {
        int u = (t >= o) ? s[t - o] : 0;
        __syncthreads();
        s[t] += u;
        __syncthreads();
    }
    if (t < nb) g_bscan[t] = s[t] - v;   // exclusive
    if (t == 0) g_off[n] = e;
}

// Stage 3: per-chunk exclusive scan + write off/cursor/dinv.
__global__ __launch_bounds__(SCAN_TPB) void scan_write_kernel(int n) {
    __shared__ int s[SCAN_TPB];
    int t = threadIdx.x;
    int i = blockIdx.x * SCAN_TPB + t;
    int d = (i < n) ? g_degi[i] : 0;
    s[t] = d;
    __syncthreads();
    for (int o = 1; o < SCAN_TPB; o <<= 1) {
        int u = (t >= o) ? s[t - o] : 0;
        __syncthreads();
        s[t] += u;
        __syncthreads();
    }
    if (i < n) {
        int off = g_bscan[blockIdx.x] + s[t] - d;  // exclusive prefix
        g_off[i] = off;
        g_cursor[i] = off;
        g_dinv[i] = rsqrtf((float)(d + 1));
    }
}

__global__ void fill_kernel(const int* __restrict__ src, const int* __restrict__ dst, int e) {
    int i = blockIdx.x * blockDim.x + threadIdx.x;
    if (i < e) {
        int d = dst[i];
        int pos = atomicAdd(&g_cursor[d], 1);
        g_csrc[pos] = src[i];
    }
}

// ---------------------------------------------------------------------------
// GEMM1: y1[n,64] = x[n,128] @ W1[128,64]   (raw, dinv folded into agg1)
// block = 256 threads; tile 32 rows x 64 cols; 2 rows x 4 cols per thread.
// ---------------------------------------------------------------------------
#define XS_LD 129
__global__ __launch_bounds__(256) void gemm1_kernel(const float* __restrict__ x,
                                                    const float* __restrict__ W1,
                                                    int n) {
    __shared__ float Ws[F_IN * F_HID];        // 32 KB, [k][c]
    __shared__ float Xs[32 * XS_LD];          // ~16.5 KB, [r][k] padded
    int tid = threadIdx.x;
    int row0 = blockIdx.x * 32;

    for (int i = tid; i < F_IN * F_HID; i += 256) Ws[i] = W1[i];
    for (int i = tid; i < 32 * F_IN; i += 256) {
        int r = i >> 7, k = i & 127;
        int gr = row0 + r;
        Xs[r * XS_LD + k] = (gr < n) ? x[gr * F_IN + k] : 0.f;
    }
    __syncthreads();

    int tx = tid & 15;        // cols tx*4 .. tx*4+3
    int ty = tid >> 4;        // 0..15, rows ty*2, ty*2+1
    float4 acc0 = make_float4(0.f, 0.f, 0.f, 0.f);
    float4 acc1 = make_float4(0.f, 0.f, 0.f, 0.f);
    const float4* Ws4 = reinterpret_cast<const float4*>(Ws);
    int r0 = ty * 2, r1 = ty * 2 + 1;
    #pragma unroll 4
    for (int k = 0; k < F_IN; k++) {
        float4 w = Ws4[k * 16 + tx];
        float a0 = Xs[r0 * XS_LD + k];
        float a1 = Xs[r1 * XS_LD + k];
        acc0.x = fmaf(a0, w.x, acc0.x); acc0.y = fmaf(a0, w.y, acc0.y);
        acc0.z = fmaf(a0, w.z, acc0.z); acc0.w = fmaf(a0, w.w, acc0.w);
        acc1.x = fmaf(a1, w.x, acc1.x); acc1.y = fmaf(a1, w.y, acc1.y);
        acc1.z = fmaf(a1, w.z, acc1.z); acc1.w = fmaf(a1, w.w, acc1.w);
    }
    int gr0 = row0 + r0, gr1 = row0 + r1;
    float4* y4 = reinterpret_cast<float4*>(g_y1);
    if (gr0 < n) y4[gr0 * 16 + tx] = acc0;
    if (gr1 < n) y4[gr1 * 16 + tx] = acc1;
}

// ---------------------------------------------------------------------------
// Aggregation layer 1 (warp per dst node, index-prefetch + shuffle):
//   acc = dinv[d]*y1[d] + sum_s dinv[s]*y1[s]
//   h[d] = relu(dinv[d]*acc + b1)
// ---------------------------------------------------------------------------
__global__ __launch_bounds__(256) void agg1_kernel(const float* __restrict__ b1, int n) {
    int w = (blockIdx.x * blockDim.x + threadIdx.x) >> 5;
    int l = threadIdx.x & 31;
    if (w >= n) return;
    const float2* y = reinterpret_cast<const float2*>(g_y1);

    float diw = g_dinv[w];
    float2 sv = y[w * 32 + l];
    float2 acc = make_float2(sv.x * diw, sv.y * diw);   // self-loop term

    int beg = g_off[w], end = g_off[w + 1];
    for (int j = beg; j < end; j += 32) {
        int m = min(32, end - j);
        int idx = 0; float dv = 0.f;
        if (l < m) { idx = g_csrc[j + l]; dv = g_dinv[idx]; }
        int t = 0;
        for (; t + 3 < m; t += 4) {
            int   s0 = __shfl_sync(0xFFFFFFFFu, idx, t    );
            int   s1 = __shfl_sync(0xFFFFFFFFu, idx, t + 1);
            int   s2 = __shfl_sync(0xFFFFFFFFu, idx, t + 2);
            int   s3 = __shfl_sync(0xFFFFFFFFu, idx, t + 3);
            float d0 = __shfl_sync(0xFFFFFFFFu, dv,  t    );
            float d1 = __shfl_sync(0xFFFFFFFFu, dv,  t + 1);
            float d2 = __shfl_sync(0xFFFFFFFFu, dv,  t + 2);
            float d3 = __shfl_sync(0xFFFFFFFFu, dv,  t + 3);
            float2 v0 = y[s0 * 32 + l];
            float2 v1 = y[s1 * 32 + l];
            float2 v2 = y[s2 * 32 + l];
            float2 v3 = y[s3 * 32 + l];
            acc.x = fmaf(v0.x, d0, acc.x); acc.y = fmaf(v0.y, d0, acc.y);
            acc.x = fmaf(v1.x, d1, acc.x); acc.y = fmaf(v1.y, d1, acc.y);
            acc.x = fmaf(v2.x, d2, acc.x); acc.y = fmaf(v2.y, d2, acc.y);
            acc.x = fmaf(v3.x, d3, acc.x); acc.y = fmaf(v3.y, d3, acc.y);
        }
        for (; t < m; t++) {
            int   s0 = __shfl_sync(0xFFFFFFFFu, idx, t);
            float d0 = __shfl_sync(0xFFFFFFFFu, dv,  t);
            float2 v = y[s0 * 32 + l];
            acc.x = fmaf(v.x, d0, acc.x); acc.y = fmaf(v.y, d0, acc.y);
        }
    }
    float2 h;
    h.x = fmaxf(fmaf(diw, acc.x, b1[2 * l    ]), 0.f);
    h.y = fmaxf(fmaf(diw, acc.y, b1[2 * l + 1]), 0.f);
    reinterpret_cast<float2*>(g_h)[w * 32 + l] = h;
}

// ---------------------------------------------------------------------------
// GEMM2: y2[n,48] = (h[n,64] @ W2pad[64,48]) * dinv[row], col 47 = 0
// ---------------------------------------------------------------------------
#define HS_LD 65
__global__ __launch_bounds__(192) void gemm2_kernel(const float* __restrict__ W2, int n) {
    __shared__ float Ws[F_HID * F_OUTP];      // 12 KB, [k][c]
    __shared__ float Hs[64 * HS_LD];          // ~16.6 KB, [r][k] padded
    int tid = threadIdx.x;
    int row0 = blockIdx.x * 64;

    for (int i = tid; i < F_HID * F_OUTP; i += 192) {
        int k = i / F_OUTP, c = i - k * F_OUTP;
        Ws[i] = (c < F_OUT) ? W2[k * F_OUT + c] : 0.f;
    }
    for (int i = tid; i < 64 * F_HID; i += 192) {
        int r = i >> 6, k = i & 63;
        int gr = row0 + r;
        Hs[r * HS_LD + k] = (gr < n) ? g_h[gr * F_HID + k] : 0.f;
    }
    __syncthreads();

    int tx = tid % 12;        // cols tx*4..tx*4+3
    int ty = tid / 12;        // 0..15, rows ty*4..ty*4+3
    float4 acc[4];
    #pragma unroll
    for (int i = 0; i < 4; i++) acc[i] = make_float4(0.f, 0.f, 0.f, 0.f);
    const float4* Ws4 = reinterpret_cast<const float4*>(Ws);

    #pragma unroll 4
    for (int k = 0; k < F_HID; k++) {
        float4 wv = Ws4[k * 12 + tx];
        #pragma unroll
        for (int i = 0; i < 4; i++) {
            float a = Hs[(ty * 4 + i) * HS_LD + k];
            acc[i].x = fmaf(a, wv.x, acc[i].x);
            acc[i].y = fmaf(a, wv.y, acc[i].y);
            acc[i].z = fmaf(a, wv.z, acc[i].z);
            acc[i].w = fmaf(a, wv.w, acc[i].w);
        }
    }
    float4* y4 = reinterpret_cast<float4*>(g_y2);
    #pragma unroll
    for (int i = 0; i < 4; i++) {
        int r = row0 + ty * 4 + i;
        if (r < n) {
            float di = g_dinv[r];
            float4 v = acc[i];
            v.x *= di; v.y *= di; v.z *= di; v.w *= di;
            y4[r * 12 + tx] = v;
        }
    }
}

// ---------------------------------------------------------------------------
// Aggregation layer 2 + bias + log_softmax (warp per node, index-prefetch):
//   z[d] = dinv[d]*(sum y2[s] + y2[d]) + b2 ; out = z - logsumexp(z)
// ---------------------------------------------------------------------------
__global__ __launch_bounds__(256) void agg2_kernel(const float* __restrict__ b2,
                                                   float* __restrict__ out, int n) {
    int w = (blockIdx.x * blockDim.x + threadIdx.x) >> 5;
    int l = threadIdx.x & 31;
    if (w >= n) return;
    const float2* y = reinterpret_cast<const float2*>(g_y2);
    bool act = (l < 24);

    float2 acc = make_float2(0.f, 0.f);
    if (act) acc = y[w * 24 + l];     // self-loop term (y2 already scaled by dinv)

    int beg = g_off[w], end = g_off[w + 1];
    for (int j = beg; j < end; j += 32) {
        int m = min(32, end - j);
        int idx = (l < m) ? g_csrc[j + l] : 0;
        int t = 0;
        for (; t + 3 < m; t += 4) {
            int s0 = __shfl_sync(0xFFFFFFFFu, idx, t    );
            int s1 = __shfl_sync(0xFFFFFFFFu, idx, t + 1);
            int s2 = __shfl_sync(0xFFFFFFFFu, idx, t + 2);
            int s3 = __shfl_sync(0xFFFFFFFFu, idx, t + 3);
            if (act) {
                float2 v0 = y[s0 * 24 + l];
                float2 v1 = y[s1 * 24 + l];
                float2 v2 = y[s2 * 24 + l];
                float2 v3 = y[s3 * 24 + l];
                acc.x += (v0.x + v1.x) + (v2.x + v3.x);
                acc.y += (v0.y + v1.y) + (v2.y + v3.y);
            }
        }
        for (; t < m; t++) {
            int s0 = __shfl_sync(0xFFFFFFFFu, idx, t);
            if (act) {
                float2 v = y[s0 * 24 + l];
                acc.x += v.x; acc.y += v.y;
            }
        }
    }

    float di = g_dinv[w];
    float vx = -3.0e38f, vy = -3.0e38f;
    if (act) {
        vx = fmaf(di, acc.x, b2[2 * l]);
        if (2 * l + 1 < F_OUT) vy = fmaf(di, acc.y, b2[2 * l + 1]);
    }
    float m = fmaxf(vx, vy);
    #pragma unroll
    for (int o = 16; o > 0; o >>= 1)
        m = fmaxf(m, __shfl_xor_sync(0xFFFFFFFFu, m, o));
    float s = 0.f;
    if (act) {
        s = expf(vx - m);
        if (2 * l + 1 < F_OUT) s += expf(vy - m);
    }
    #pragma unroll
    for (int o = 16; o > 0; o >>= 1)
        s += __shfl_xor_sync(0xFFFFFFFFu, s, o);
    float lse = m + logf(s);

    if (act) {
        out[w * F_OUT + 2 * l] = vx - lse;
        if (2 * l + 1 < F_OUT) out[w * F_OUT + 2 * l + 1] = vy - lse;
    }
}

// ---------------------------------------------------------------------------
// Launch (stream fork: GEMM1 runs concurrently with CSR build)
// ---------------------------------------------------------------------------
extern "C" void kernel_launch(void* const* d_in, const int* in_sizes, int n_in,
                              void* d_out, int out_size) {
    const float* x  = (const float*)d_in[0];
    const int*   ei = (const int*)  d_in[1];
    const float* W1 = (const float*)d_in[2];
    const float* b1 = (const float*)d_in[3];
    const float* W2 = (const float*)d_in[4];
    const float* b2 = (const float*)d_in[5];
    float* out = (float*)d_out;

    int n = in_sizes[0] / F_IN;       // 100000
    int e = in_sizes[1] / 2;          // 1600000
    const int* src = ei;
    const int* dst = ei + e;

    static cudaStream_t s2 = nullptr;
    static cudaEvent_t ev_fork = nullptr, ev_join = nullptr;
    if (s2 == nullptr) {
        cudaStreamCreateWithFlags(&s2, cudaStreamNonBlocking);
        cudaEventCreateWithFlags(&ev_fork, cudaEventDisableTiming);
        cudaEventCreateWithFlags(&ev_join, cudaEventDisableTiming);
    }

    const int B = 256;
    int nb = (n + SCAN_TPB - 1) / SCAN_TPB;   // 196 <= 256

    // Fork: GEMM1 (independent of CSR build) on side stream
    cudaEventRecord(ev_fork, 0);
    cudaStreamWaitEvent(s2, ev_fork, 0);
    gemm1_kernel<<<(n + 31) / 32, 256, 0, s2>>>(x, W1, n);
    cudaEventRecord(ev_join, s2);

    // Main stream: CSR build
    zero_degi_kernel<<<(n + B - 1) / B, B>>>(n);
    count_kernel<<<(e + B - 1) / B, B>>>(dst, e);
    scan_partial_kernel<<<nb, SCAN_TPB>>>(n);
    scan_tops_kernel<<<1, SCAN_NB_MAX>>>(nb, n, e);
    scan_write_kernel<<<nb, SCAN_TPB>>>(n);
    fill_kernel<<<(e + B - 1) / B, B>>>(src, dst, e);

    // Join: agg1 needs both CSR (main) and y1 (s2)
    cudaStreamWaitEvent(0, ev_join, 0);

    agg1_kernel<<<(n * 32 + B - 1) / B, B>>>(b1, n);
    gemm2_kernel<<<(n + 63) / 64, 192>>>(W2, n);
    agg2_kernel<<<(n * 32 + B - 1) / B, B>>>(b2, out, n);
}